// round 16
// baseline (speedup 1.0000x reference)
#include <cuda_runtime.h>
#include <math.h>
#include <stdint.h>

#define NL 1024
#define NB 64
#define NH 512
#define NP 21
#define NLU 60
#define SMEM_LSTM 207104

typedef unsigned long long ull;

// ---------------- device scratch (static, no allocation) ----------------
__device__ float4 d_E4[2 * 20 * NH];           // [dir][sym][unit] -> 4 gate pre-acts (bias folded)
__device__ float4 d_gh[2][2][128 * 64];        // [buf][dir][kq*64+b] h in k-quad float4 layout
__device__ float  d_hs[(size_t)NL * NB * 1024];// [l][b][dir*512+j]
__device__ float  d_phi[NL * NB * 3];
__device__ float  d_tab[NLU * 6];              // [u][c][{sin,cos}]
__device__ unsigned d_flag[2][64];             // per-dir per-CTA step counters

__device__ __forceinline__ float sigf(float x) { return 1.f / (1.f + expf(-x)); }

__device__ __forceinline__ ull pk2(float lo, float hi) {
    ull r; asm("mov.b64 %0, {%1, %2};" : "=l"(r) : "f"(lo), "f"(hi)); return r;
}
__device__ __forceinline__ float2 upk2(ull v) {
    float2 f; asm("mov.b64 {%0, %1}, %2;" : "=f"(f.x), "=f"(f.y) : "l"(v)); return f;
}
#define FMA2(d, a, b) asm("fma.rn.f32x2 %0, %1, %2, %0;" : "+l"(d) : "l"(a), "l"(b))

// ---------------- init: zero h buffers + flags, sin/cos table ----------------
__global__ void k_init(const float* __restrict__ alphabet) {
    int idx = blockIdx.x * 256 + threadIdx.x;
    float4* g = &d_gh[0][0][0];
    if (idx < 2 * 2 * 128 * 64) g[idx] = make_float4(0.f, 0.f, 0.f, 0.f);
    if (idx < 128) ((unsigned*)d_flag)[idx] = 0u;
    if (idx < NLU) {
        #pragma unroll
        for (int c = 0; c < 3; c++) {
            float s, co;
            sincosf(alphabet[idx * 3 + c], &s, &co);
            d_tab[idx * 6 + c * 2 + 0] = s;
            d_tab[idx * 6 + c * 2 + 1] = co;
        }
    }
}

// ---------------- E table: E4[d][s][j].q = embed[s] . Wih_d[q*512+j, :512] + bias ----------------
__global__ void k_embed(const float* __restrict__ embed,
                        const float* __restrict__ Wih_f, const float* __restrict__ bih_f, const float* __restrict__ bhh_f,
                        const float* __restrict__ Wih_b, const float* __restrict__ bih_b, const float* __restrict__ bhh_b) {
    int w = (blockIdx.x * blockDim.x + threadIdx.x) >> 5;  // 4096 gate rows
    int lane = threadIdx.x & 31;
    if (w >= 4096) return;
    int d = w >> 11, g = w & 2047, q = g >> 9, j = g & 511;
    const float* Wih = d ? Wih_b : Wih_f;
    float bias = d ? (bih_b[g] + bhh_b[g]) : (bih_f[g] + bhh_f[g]);
    const float* wrow = Wih + (size_t)g * 533;
    float wr[16];
    #pragma unroll
    for (int i = 0; i < 16; i++) wr[i] = wrow[lane + i * 32];
    for (int s = 0; s < 20; s++) {
        const float* er = embed + s * 512;
        float acc = 0.f;
        #pragma unroll
        for (int i = 0; i < 16; i++) acc += er[lane + i * 32] * wr[i];
        #pragma unroll
        for (int o = 16; o; o >>= 1) acc += __shfl_xor_sync(0xffffffffu, acc, o);
        if (lane == 0)
            ((float*)d_E4)[(((d * 20 + s) * 512) + j) * 4 + q] = acc + bias;
    }
}

// ---------------- persistent biLSTM: CTA = {dir, 8 units}, warp = 1 unit, lane = 2 batches ----------------
__global__ void __launch_bounds__(256, 1) k_lstm(
    const int* __restrict__ seq, const float* __restrict__ pssm,
    const float* __restrict__ Whh_f, const float* __restrict__ Whh_b,
    const float* __restrict__ Wih_f, const float* __restrict__ Wih_b)
{
    extern __shared__ float smf[];
    float4* Wsm  = (float4*)smf;           // [8 u][128 kq][4 q]    4096 f4 (64KB)
    float4* hQ   = Wsm + 4096;             // [128 kq][64 b]        8192 f4 (128KB)
    float*  psmF = (float*)(hQ + 8192);    // [64 b][22]            1408 fl
    float*  WpF  = psmF + 1408;            // [8 u][4 q][22]        704 fl
    float*  h8   = WpF + 704;              // [64 b][8 u]           512 fl

    const int tid = threadIdx.x;
    const int dir = blockIdx.x >> 6;
    const int ub  = blockIdx.x & 63;
    const float* Whh = dir ? Whh_b : Whh_f;
    const float* Wih = dir ? Wih_b : Wih_f;

    // one-time: Whh slice  Wsm[u*512 + kq*4 + q] = Whh[q*512+ub*8+u][4kq..4kq+3]
    for (int s = tid; s < 4096; s += 256) {
        int u = s >> 9, kq = (s >> 2) & 127, q = s & 3;
        Wsm[s] = *((const float4*)(Whh + (size_t)(q * 512 + ub * 8 + u) * 512) + kq);
    }
    // one-time: pssm weights  WpF[(u*4+q)*22 + jj], jj padded to 22 with 0
    for (int s = tid; s < 672; s += 256) {
        int u = s / 84, rr = s % 84, q = rr / 21, jj = rr % 21;
        WpF[(u * 4 + q) * 22 + jj] = Wih[(size_t)(q * 512 + ub * 8 + u) * 533 + 512 + jj];
    }
    if (tid < 32) WpF[tid * 22 + 21] = 0.f;
    if (tid < 64) psmF[tid * 22 + 21] = 0.f;   // pad, never overwritten

    const int u = tid >> 5, lane = tid & 31;
    const int j = ub * 8 + u;
    float cst[2] = {0.f, 0.f};
    uint32_t hq_s  = (uint32_t)__cvta_generic_to_shared(hQ);
    uint32_t psm_s = (uint32_t)__cvta_generic_to_shared(psmF);

    __syncthreads();   // Wsm/WpF staged

    for (int r = 0; r < NL; r++) {
        const int t = dir ? (NL - 1 - r) : r;
        const int rb = r & 1;
        const float4* src = d_gh[rb][dir];

        // --- independent of h: issue early, hide under the flag wait ---
        int s0 = seq[t * NB + lane];
        int s1 = seq[t * NB + 32 + lane];
        {   // pssm row via 4B cp.async into padded [b][22] layout  (group: pssm)
            const float* sp = pssm + (size_t)t * (NB * NP);
            for (int i = tid; i < NB * NP; i += 256) {
                int b = i / 21, jj = i - b * 21;
                asm volatile("cp.async.ca.shared.global [%0], [%1], 4;"
                             :: "r"(psm_s + (b * 22 + jj) * 4), "l"(sp + i) : "memory");
            }
            asm volatile("cp.async.commit_group;" ::: "memory");
        }

        // --- wait for this dir's 64 producers to publish buffer rb ---
        if (tid < 64) {
            unsigned tgt = (unsigned)r, v;
            const unsigned* fp = &d_flag[dir][tid];
            do {
                asm volatile("ld.acquire.gpu.global.u32 %0, [%1];" : "=r"(v) : "l"(fp));
            } while (v < tgt);
        }
        __syncthreads();

        // --- async-stage h in 4 groups of 32 kq (32KB each) ---
        #pragma unroll
        for (int g = 0; g < 4; g++) {
            #pragma unroll
            for (int i = 0; i < 8; i++) {
                int idx = tid + (g * 8 + i) * 256;
                asm volatile("cp.async.cg.shared.global [%0], [%1], 16;"
                             :: "r"(hq_s + idx * 16), "l"(src + idx) : "memory");
            }
            asm volatile("cp.async.commit_group;" ::: "memory");
        }

        // --- init accumulators from E table (input GEMM + bias folded; lo lane) ---
        float4 e0 = d_E4[(dir * 20 + s0) * 512 + j];
        float4 e1 = d_E4[(dir * 20 + s1) * 512 + j];
        ull acc[4][2];
        acc[0][0] = pk2(e0.x, 0.f); acc[1][0] = pk2(e0.y, 0.f);
        acc[2][0] = pk2(e0.z, 0.f); acc[3][0] = pk2(e0.w, 0.f);
        acc[0][1] = pk2(e1.x, 0.f); acc[1][1] = pk2(e1.y, 0.f);
        acc[2][1] = pk2(e1.z, 0.f); acc[3][1] = pk2(e1.w, 0.f);

        // --- pssm contribution (wait pssm group; 4 h groups still pending) ---
        asm volatile("cp.async.wait_group 4;" ::: "memory");
        __syncthreads();
        {
            const ull* pp0 = (const ull*)(psmF + lane * 22);
            const ull* pp1 = (const ull*)(psmF + (lane + 32) * 22);
            const ull* wp  = (const ull*)(WpF + (u * 4) * 22);
            #pragma unroll
            for (int tt = 0; tt < 11; tt++) {
                ull p0 = pp0[tt], p1 = pp1[tt];
                #pragma unroll
                for (int q = 0; q < 4; q++) {
                    ull wv = wp[q * 11 + tt];
                    FMA2(acc[q][0], wv, p0);
                    FMA2(acc[q][1], wv, p1);
                }
            }
        }

        // --- recurrent GEMM: 4 pipelined groups of 32 k-quads ---
        const ulonglong2* Wb = (const ulonglong2*)(Wsm + (u << 9));
        #pragma unroll
        for (int g = 0; g < 4; g++) {
            if      (g == 0) asm volatile("cp.async.wait_group 3;" ::: "memory");
            else if (g == 1) asm volatile("cp.async.wait_group 2;" ::: "memory");
            else if (g == 2) asm volatile("cp.async.wait_group 1;" ::: "memory");
            else             asm volatile("cp.async.wait_group 0;" ::: "memory");
            __syncthreads();
            #pragma unroll 4
            for (int kq = g * 32; kq < g * 32 + 32; kq++) {
                ulonglong2 ha = *(const ulonglong2*)(hQ + (kq << 6) + lane);
                ulonglong2 hb = *(const ulonglong2*)(hQ + (kq << 6) + 32 + lane);
                const ulonglong2* Wk = Wb + (kq << 2);   // 4 gate float4s = 4 ulonglong2 per kq
                ulonglong2 w0 = Wk[0];
                ulonglong2 w1 = Wk[1];
                FMA2(acc[0][0], w0.x, ha.x); FMA2(acc[0][0], w0.y, ha.y);
                FMA2(acc[0][1], w0.x, hb.x); FMA2(acc[0][1], w0.y, hb.y);
                FMA2(acc[1][0], w1.x, ha.x); FMA2(acc[1][0], w1.y, ha.y);
                FMA2(acc[1][1], w1.x, hb.x); FMA2(acc[1][1], w1.y, hb.y);
                ulonglong2 w2 = Wk[2];
                ulonglong2 w3 = Wk[3];
                FMA2(acc[2][0], w2.x, ha.x); FMA2(acc[2][0], w2.y, ha.y);
                FMA2(acc[2][1], w2.x, hb.x); FMA2(acc[2][1], w2.y, hb.y);
                FMA2(acc[3][0], w3.x, ha.x); FMA2(acc[3][0], w3.y, ha.y);
                FMA2(acc[3][1], w3.x, hb.x); FMA2(acc[3][1], w3.y, hb.y);
            }
        }

        // --- gates (torch order i,f,g,o) + publish ---
        float* gw = (float*)(d_gh[rb ^ 1][dir]);
        #pragma unroll
        for (int bb = 0; bb < 2; bb++) {
            float2 zi = upk2(acc[0][bb]);
            float2 zf = upk2(acc[1][bb]);
            float2 zg = upk2(acc[2][bb]);
            float2 zo = upk2(acc[3][bb]);
            float ig = sigf(zi.x + zi.y);
            float fg = sigf(zf.x + zf.y);
            float gg = tanhf(zg.x + zg.y);
            float og = sigf(zo.x + zo.y);
            float c = fg * cst[bb] + ig * gg;
            cst[bb] = c;
            float hh = og * tanhf(c);
            int b = lane + bb * 32;
            gw[((j >> 2) * 64 + b) * 4 + (j & 3)] = hh;
            h8[b * 8 + u] = hh;
        }

        __syncthreads();   // publish STGs + h8 ordered block-wide
        #pragma unroll
        for (int v = 0; v < 2; v++) {
            int s = tid + v * 256;
            d_hs[(size_t)(t * 64 + (s >> 3)) * 1024 + dir * 512 + ub * 8 + (s & 7)] = h8[s];
        }
        if (tid == 0)
            asm volatile("st.release.gpu.global.u32 [%0], %1;"
                         :: "l"(&d_flag[dir][ub]), "r"(r + 1) : "memory");
    }
}

// ---------------- logits + softmax + angularization: 64-row x 64-u tiled f32x2 GEMM ----------------
__global__ void __launch_bounds__(256) k_logits(const float* __restrict__ W_lin,
                                                const float* __restrict__ b_lin) {
    __shared__ float hT[64 * 66];
    __shared__ ull   wT[32 * 64];
    const int tid = threadIdx.x;
    const int row0 = blockIdx.x * 64;
    const int tu = tid & 15, tr = tid >> 4;

    ull acc[4][4];
    #pragma unroll
    for (int i = 0; i < 4; i++)
        #pragma unroll
        for (int jj = 0; jj < 4; jj++) acc[i][jj] = 0ull;

    for (int kc = 0; kc < 16; kc++) {
        #pragma unroll
        for (int v = 0; v < 4; v++) {
            int s = tid + v * 256;          // 0..1023
            int rr = s >> 4, seg = s & 15;
            float4 hv = *(const float4*)(d_hs + (size_t)(row0 + rr) * 1024 + kc * 64 + seg * 4);
            float* dst = hT + rr * 66 + seg * 4;
            dst[0] = hv.x; dst[1] = hv.y; dst[2] = hv.z; dst[3] = hv.w;
        }
        #pragma unroll
        for (int v = 0; v < 8; v++) {
            int s = tid + v * 256;          // 0..2047
            int uu = s >> 5, kp = s & 31;
            ull val = 0ull;
            if (uu < NLU) val = *(const ull*)(W_lin + (size_t)uu * 1024 + kc * 64 + kp * 2);
            wT[kp * 64 + uu] = val;
        }
        __syncthreads();
        #pragma unroll 4
        for (int kp = 0; kp < 32; kp++) {
            ulonglong2 wA = *(const ulonglong2*)(wT + kp * 64 + tu * 4);
            ulonglong2 wB = *(const ulonglong2*)(wT + kp * 64 + tu * 4 + 2);
            #pragma unroll
            for (int i = 0; i < 4; i++) {
                ull hv = *(const ull*)(hT + (tr * 4 + i) * 66 + kp * 2);
                FMA2(acc[i][0], wA.x, hv);
                FMA2(acc[i][1], wA.y, hv);
                FMA2(acc[i][2], wB.x, hv);
                FMA2(acc[i][3], wB.y, hv);
            }
        }
        __syncthreads();
    }

    // per-row softmax + angularization; row owned by 16 tu-lanes
    #pragma unroll
    for (int i = 0; i < 4; i++) {
        int row = row0 + tr * 4 + i;
        float z[4];
        #pragma unroll
        for (int jj = 0; jj < 4; jj++) {
            int uu = tu * 4 + jj;
            float2 f = upk2(acc[i][jj]);
            z[jj] = (uu < NLU) ? (f.x + f.y + b_lin[uu]) : -3.4e38f;
        }
        float m = fmaxf(fmaxf(z[0], z[1]), fmaxf(z[2], z[3]));
        #pragma unroll
        for (int o = 8; o; o >>= 1) m = fmaxf(m, __shfl_xor_sync(0xffffffffu, m, o));
        float e[4], s = 0.f;
        #pragma unroll
        for (int jj = 0; jj < 4; jj++) { e[jj] = expf(z[jj] - m); s += e[jj]; }
        #pragma unroll
        for (int o = 8; o; o >>= 1) s += __shfl_xor_sync(0xffffffffu, s, o);
        float inv = 1.f / s;
        float sA = 0.f, cA = 0.f, sB = 0.f, cB = 0.f, sC = 0.f, cC = 0.f;
        #pragma unroll
        for (int jj = 0; jj < 4; jj++) {
            int uu = tu * 4 + jj;
            if (uu < NLU) {
                float p = e[jj] * inv;
                const float* tb = d_tab + uu * 6;
                sA += p * tb[0]; cA += p * tb[1];
                sB += p * tb[2]; cB += p * tb[3];
                sC += p * tb[4]; cC += p * tb[5];
            }
        }
        #pragma unroll
        for (int o = 8; o; o >>= 1) {
            sA += __shfl_xor_sync(0xffffffffu, sA, o);
            cA += __shfl_xor_sync(0xffffffffu, cA, o);
            sB += __shfl_xor_sync(0xffffffffu, sB, o);
            cB += __shfl_xor_sync(0xffffffffu, cB, o);
            sC += __shfl_xor_sync(0xffffffffu, sC, o);
            cC += __shfl_xor_sync(0xffffffffu, cC, o);
        }
        if (tu == 0) {
            d_phi[row * 3 + 0] = atan2f(sA, cA);
            d_phi[row * 3 + 1] = atan2f(sB, cB);
            d_phi[row * 3 + 2] = atan2f(sC, cC);
        }
    }
}

// ---------------- NeRF chain extension (thread per batch) ----------------
__global__ void k_geom(float* __restrict__ out) {
    int b = threadIdx.x;
    if (b >= NB) return;
    const float BL[3] = {132.868f, 145.801f, 152.326f};
    const float BA[3] = {2.028f, 2.124f, 1.941f};
    float cT[3], sT[3];
    #pragma unroll
    for (int jj = 0; jj < 3; jj++) sincosf(BA[jj], &sT[jj], &cT[jj]);

    float Ax = 1.f, Ay = 0.f, Az = 0.f;
    float Bx = 0.f, By = 1.f, Bz = 0.f;
    float Cx = 0.f, Cy = 0.f, Cz = 1.f;
    #pragma unroll
    for (int r = 0; r < 3; r++)
        #pragma unroll
        for (int c = 0; c < 3; c++)
            out[((size_t)r * 64 + b) * 3 + c] = (r == c) ? 1.f : 0.f;

    for (int i = 0; i < NL; i++) {
        #pragma unroll
        for (int jj = 0; jj < 3; jj++) {
            float P = d_phi[((size_t)i * 64 + b) * 3 + jj];
            float sp, cp;
            sincosf(P, &sp, &cp);
            float D2x = -BL[jj] * cT[jj];
            float D2y =  BL[jj] * cp * sT[jj];
            float D2z =  BL[jj] * sp * sT[jj];
            float bcx = Cx - Bx, bcy = Cy - By, bcz = Cz - Bz;
            float il = 1.f / sqrtf(bcx * bcx + bcy * bcy + bcz * bcz);
            bcx *= il; bcy *= il; bcz *= il;
            float abx = Bx - Ax, aby = By - Ay, abz = Bz - Az;
            float nx = aby * bcz - abz * bcy;
            float ny = abz * bcx - abx * bcz;
            float nz = abx * bcy - aby * bcx;
            float iln = 1.f / sqrtf(nx * nx + ny * ny + nz * nz);
            nx *= iln; ny *= iln; nz *= iln;
            float mx = ny * bcz - nz * bcy;
            float my = nz * bcx - nx * bcz;
            float mz = nx * bcy - ny * bcx;
            float Dx = D2x * bcx + D2y * mx + D2z * nx + Cx;
            float Dy = D2x * bcy + D2y * my + D2z * ny + Cy;
            float Dz = D2x * bcz + D2y * mz + D2z * nz + Cz;
            size_t rw = (size_t)(3 + i * 3 + jj) * 64 + b;
            out[rw * 3 + 0] = Dx; out[rw * 3 + 1] = Dy; out[rw * 3 + 2] = Dz;
            Ax = Bx; Ay = By; Az = Bz;
            Bx = Cx; By = Cy; Bz = Cz;
            Cx = Dx; Cy = Dy; Cz = Dz;
        }
    }
}

extern "C" void kernel_launch(void* const* d_in, const int* in_sizes, int n_in,
                              void* d_out, int out_size) {
    const int*   seq      = (const int*)d_in[0];
    const float* pssm     = (const float*)d_in[1];
    // d_in[2] = length (unused: all full-length)
    const float* embed    = (const float*)d_in[3];
    const float* Wih_f    = (const float*)d_in[4];
    const float* Whh_f    = (const float*)d_in[5];
    const float* bih_f    = (const float*)d_in[6];
    const float* bhh_f    = (const float*)d_in[7];
    const float* Wih_b    = (const float*)d_in[8];
    const float* Whh_b    = (const float*)d_in[9];
    const float* bih_b    = (const float*)d_in[10];
    const float* bhh_b    = (const float*)d_in[11];
    const float* W_lin    = (const float*)d_in[12];
    const float* b_lin    = (const float*)d_in[13];
    const float* alphabet = (const float*)d_in[14];
    float* out = (float*)d_out;

    cudaFuncSetAttribute(k_lstm, cudaFuncAttributeMaxDynamicSharedMemorySize, SMEM_LSTM);

    k_init<<<128, 256>>>(alphabet);
    k_embed<<<512, 256>>>(embed, Wih_f, bih_f, bhh_f, Wih_b, bih_b, bhh_b);
    k_lstm<<<128, 256, SMEM_LSTM>>>(seq, pssm, Whh_f, Whh_b, Wih_f, Wih_b);
    k_logits<<<NL * NB / 64, 256>>>(W_lin, b_lin);
    k_geom<<<1, 64>>>(out);
}